// round 16
// baseline (speedup 1.0000x reference)
#include <cuda_runtime.h>

// x shape [3, 5, 32, 64, 32, 32] -> 30720 images of 32x32
#define N_IMGS   30720
#define N_OUT    480
#define PATCHES  64
#define HW       1024
#define WPB      8          // warps (=images) per block
#define MAXRUNS  512        // <= 16 runs/row * 32 rows
#define MAXEDGES 384        // typical ~200; overflow handled by direct merge

// Cross-block accumulation scratch; self-resetting each replay.
__device__ int g_sum[N_OUT];
__device__ int g_cnt[N_OUT];

// UF entry (merge phase): plain parent id. Count phase: upper 16 bits of each
// ROOT accumulate the component total via atomicAdd(sz<<16); parent id stays
// in the low bits (ids < 512, sums <= 1024 — never carries).

__device__ __forceinline__ int ufind(int* P, int a) {
    while (true) {
        int p = P[a];
        if (p == a) return a;
        int gp = P[p];
        if (gp == p) return p;
        P[a] = gp;              // path halving
        a = gp;
    }
}

// Merge; returns surviving (min) root as a find hint for the caller.
__device__ __forceinline__ int umerge(int* P, int a, int b) {
    while (true) {
        a = ufind(P, a);
        b = ufind(P, b);
        if (a == b) return a;
        int mn = min(a, b), mx = max(a, b);
        int old = atomicMin(&P[mx], mn);
        if (old == mx) return mn;   // linked root mx -> mn
        a = mn; b = old;            // lost race; merge survivors
    }
}

// Count-phase find: parent in low 16 bits (upper bits of roots hold counts).
__device__ __forceinline__ int ufind_cnt(const int* P, int a) {
    int p = P[a] & 0xffff;
    while (p != a) { a = p; p = P[a] & 0xffff; }
    return a;
}

// Isolate lowest maximal run of 1s (low = lowest set bit of rem).
__device__ __forceinline__ unsigned lowest_run(unsigned rem, unsigned low) {
    return rem & (rem ^ (rem + low));
}

// Spread 8 bits so bit k lands at position 4k.
__device__ __forceinline__ unsigned spread4(unsigned x) {
    x = (x | (x << 12)) & 0x000F000Fu;
    x = (x | (x << 6))  & 0x03030303u;
    x = (x | (x << 3))  & 0x11111111u;
    return x;
}

// One warp per 32x32 image; lane = row.
__global__ void __launch_bounds__(32 * WPB, 8)
ccl_kernel(const float* __restrict__ x, float* __restrict__ out) {
    __shared__ int UF[WPB][MAXRUNS];
    __shared__ unsigned ED[WPB][MAXEDGES];

    const int lane = threadIdx.x & 31;
    const int warp = threadIdx.x >> 5;
    const int img  = blockIdx.x * WPB + warp;

    // ---- Row bitmasks: 8 COALESCED float4 loads, 4 ballots each ----
    const float4* p4 = (const float4*)(x + (size_t)img * HW);
    unsigned c0 = 0, c1 = 0, c2 = 0, c3 = 0;
    #pragma unroll
    for (int i = 0; i < 8; i++) {
        float4 v = __ldcs(&p4[i * 32 + lane]);
        unsigned b0 = __ballot_sync(0xFFFFFFFFu, v.x != 0.0f);
        unsigned b1 = __ballot_sync(0xFFFFFFFFu, v.y != 0.0f);
        unsigned b2 = __ballot_sync(0xFFFFFFFFu, v.z != 0.0f);
        unsigned b3 = __ballot_sync(0xFFFFFFFFu, v.w != 0.0f);
        if ((lane >> 2) == i) {
            int sh = (lane & 3) * 8;
            c0 = (b0 >> sh) & 0xffu;
            c1 = (b1 >> sh) & 0xffu;
            c2 = (b2 >> sh) & 0xffu;
            c3 = (b3 >> sh) & 0xffu;
        }
    }
    const unsigned m = spread4(c0) | (spread4(c1) << 1)
                     | (spread4(c2) << 2) | (spread4(c3) << 3);

    // ---- Run starts; per-row run-id base via warp scan ----
    const unsigned start = m & ~(m << 1);
    const int nmine = __popc(start);
    int scan = nmine;
    #pragma unroll
    for (int o = 1; o < 32; o <<= 1) {
        int v = __shfl_up_sync(0xFFFFFFFFu, scan, o);
        if (lane >= o) scan += v;
    }
    const int base  = scan - nmine;
    const int total = __shfl_sync(0xFFFFFFFFu, scan, 31);

    // ---- Init: balanced, parent = self ----
    int* uf = UF[warp];
    for (int i = lane; i < total; i += 32) uf[i] = i;

    // ---- Edge enumeration into a SORTED per-warp worklist ----
    unsigned nm     = __shfl_down_sync(0xFFFFFFFFu, m, 1);
    unsigned nstart = __shfl_down_sync(0xFFFFFFFFu, start, 1);
    int      nbase  = __shfl_down_sync(0xFFFFFFFFu, base, 1);
    if (lane == 31) nm = 0;

    unsigned ov   = m & nm;
    unsigned segs = ov & ~(ov << 1);
    const int ec = __popc(segs);           // this lane's edge count
    int escan = ec;
    #pragma unroll
    for (int o = 1; o < 32; o <<= 1) {
        int v = __shfl_up_sync(0xFFFFFFFFu, escan, o);
        if (lane >= o) escan += v;
    }
    const int eoff = escan - ec;
    const int ne   = __shfl_sync(0xFFFFFFFFu, escan, 31);

    unsigned* ed = ED[warp];
    __syncwarp();                          // uf init visible before any fallback merge
    {
        int widx = eoff;
        unsigned s2 = segs;
        while (s2) {
            int j = __ffs(s2) - 1;
            s2 &= s2 - 1;
            unsigned below = (2u << j) - 1;            // bits 0..j (j=31 -> all)
            int a = base  + __popc(start  & below) - 1;
            int b = nbase + __popc(nstart & below) - 1;
            if (widx < MAXEDGES) ed[widx++] = ((unsigned)a << 16) | (unsigned)b;
            else umerge(uf, a, b);                     // overflow fallback (rare)
        }
    }
    __syncwarp();

    // ---- Balanced CHUNKED edge processing: each lane takes a contiguous,
    //      row-sorted slice (spatially local -> hint cache stays effective).
    {
        const int ne_c  = min(ne, MAXEDGES);
        const int chunk = (ne_c + 31) >> 5;
        const int s     = lane * chunk;
        const int e     = min(s + chunk, ne_c);
        int prev_a = -1, hint = -1;
        for (int i = s; i < e; i++) {
            unsigned w = ed[i];
            int a = (int)(w >> 16), b = (int)(w & 0xffffu);
            hint = umerge(uf, (a == prev_a) ? hint : a, b);
            prev_a = a;
        }
    }
    __syncwarp();

    // ---- Count + max: each run adds its size into root's UPPER 16 bits;
    //      the LAST adder to a root observes the component's final total.
    int v = 0;
    {
        unsigned rem = m;
        int idx = base;
        while (rem) {
            unsigned low   = rem & (unsigned)(-(int)rem);
            unsigned rmask = lowest_run(rem, low);
            rem &= ~rmask;
            int sz = __popc(rmask);
            int r  = ufind_cnt(uf, idx);
            int old = atomicAdd(&uf[r], sz << 16);
            v = max(v, (old >> 16) + sz);              // last adder sees total
            idx++;
        }
    }

    // ---- Warp reductions via REDUX; background count competes for the max ----
    v = __reduce_max_sync(0xFFFFFFFFu, v);
    int bg = __reduce_add_sync(0xFFFFFFFFu, 32 - __popc(m));

    // ---- Fused reduction: 64th arriver per group finishes the output ----
    if (lane == 0) {
        const int my = max(v, bg);
        const int o = img >> 6;                        // img / PATCHES
        atomicAdd(&g_sum[o], my);
        __threadfence();
        int n = atomicAdd(&g_cnt[o], 1);
        if (n == PATCHES - 1) {
            __threadfence();
            int total_s = atomicExch(&g_sum[o], 0);    // read + reset for replay
            out[o] = (float)(total_s / PATCHES);       // truncating int divide
            atomicExch(&g_cnt[o], 0);                  // reset for replay
        }
    }
}

extern "C" void kernel_launch(void* const* d_in, const int* in_sizes, int n_in,
                              void* d_out, int out_size) {
    const float* x = (const float*)d_in[0];
    float* out = (float*)d_out;
    ccl_kernel<<<N_IMGS / WPB, 32 * WPB>>>(x, out);
}